// round 1
// baseline (speedup 1.0000x reference)
#include <cuda_runtime.h>
#include <cstdint>
#include <math_constants.h>

#define KTOP      30
#define COLS      1024
#define WPB       8            // warps (rows) per block
#define TPB       (WPB * 32)
#define MAX_BLOCKS 16384       // 131072 rows / 8
#define CAND_CAP  128          // candidate slots per warp

// deterministic partial sums (no device mallocs allowed)
__device__ float g_pcnt[MAX_BLOCKS];
__device__ float g_pdiff[MAX_BLOCKS];

// ---------- monotone float<->uint key (only used in the cold fallback) ----------
__device__ __forceinline__ unsigned fmono(float f) {
    unsigned u = __float_as_uint(f);
    return u ^ (0x80000000u | (unsigned)((int)u >> 31));
}
__device__ __forceinline__ float fdemono(unsigned k) {
    unsigned u = k ^ (0x80000000u | ~(unsigned)((int)k >> 31));
    return __uint_as_float(u);
}

// ---------- cross-lane bitonic: 4 regs/lane (128 values) -> top-32 sorted desc ----------
// returns s: lane k holds the (k+1)-th largest value of the 128 inputs
__device__ __forceinline__ float sort_top32(float v0, float v1, float v2, float v3,
                                            unsigned lane) {
    // Stage A: sort each register slice (32 values across lanes), alternating dirs,
    // final k=32 pass leaves each slice descending.
    #pragma unroll
    for (int k = 2; k <= 32; k <<= 1) {
        #pragma unroll
        for (int j = k >> 1; j >= 1; j >>= 1) {
            bool wmax = (((lane & k) == 0) == ((lane & j) == 0));
            float o0 = __shfl_xor_sync(0xffffffffu, v0, j);
            float o1 = __shfl_xor_sync(0xffffffffu, v1, j);
            float o2 = __shfl_xor_sync(0xffffffffu, v2, j);
            float o3 = __shfl_xor_sync(0xffffffffu, v3, j);
            v0 = wmax ? fmaxf(v0, o0) : fminf(v0, o0);
            v1 = wmax ? fmaxf(v1, o1) : fminf(v1, o1);
            v2 = wmax ? fmaxf(v2, o2) : fminf(v2, o2);
            v3 = wmax ? fmaxf(v3, o3) : fminf(v3, o3);
        }
    }
    // Stage B: merge pairs, keeping top-32: c[i] = max(a[i], b[31-i]) is the top-32
    // multiset and bitonic; clean with a descending bitonic merge network.
    float b1 = __shfl_sync(0xffffffffu, v1, 31 ^ lane);
    float b3 = __shfl_sync(0xffffffffu, v3, 31 ^ lane);
    float m0 = fmaxf(v0, b1);
    float m1 = fmaxf(v2, b3);
    #pragma unroll
    for (int j = 16; j >= 1; j >>= 1) {
        float o0 = __shfl_xor_sync(0xffffffffu, m0, j);
        float o1 = __shfl_xor_sync(0xffffffffu, m1, j);
        bool wmax = ((lane & j) == 0);
        m0 = wmax ? fmaxf(m0, o0) : fminf(m0, o0);
        m1 = wmax ? fmaxf(m1, o1) : fminf(m1, o1);
    }
    // Stage C: final merge of the two sorted-32 lists
    float bb = __shfl_sync(0xffffffffu, m1, 31 ^ lane);
    float s = fmaxf(m0, bb);
    #pragma unroll
    for (int j = 16; j >= 1; j >>= 1) {
        float o = __shfl_xor_sync(0xffffffffu, s, j);
        s = ((lane & j) == 0) ? fmaxf(s, o) : fminf(s, o);
    }
    return s;
}

// ---------- count elements >= Tge, warp-exclusive scan for compaction offsets ----------
__device__ __forceinline__ void count_scan(const float4 (&v)[8], float Tge, unsigned lane,
                                           int &cnt, int &base, int &total) {
    int c = 0;
    #pragma unroll
    for (int i = 0; i < 8; i++) {
        c += (v[i].x >= Tge) + (v[i].y >= Tge) + (v[i].z >= Tge) + (v[i].w >= Tge);
    }
    int incl = c;
    #pragma unroll
    for (int d = 1; d < 32; d <<= 1) {
        int n = __shfl_up_sync(0xffffffffu, incl, d);
        if ((int)lane >= d) incl += n;
    }
    total = __shfl_sync(0xffffffffu, incl, 31);
    base  = incl - c;
    cnt   = c;
}

// ---------- exact fallback: binary-search the 30th-largest value (cold path) ----------
__device__ __forceinline__ float find_thresh(const float4 (&v)[8], unsigned lane) {
    unsigned lo = 0u, hi = 0xFFFFFFFFu;   // invariant: count(key >= lo) >= KTOP
    while (lo < hi) {
        unsigned mid = lo + 1u + ((hi - lo - 1u) >> 1);   // overflow-safe upper mid
        int c = 0;
        #pragma unroll
        for (int i = 0; i < 8; i++) {
            c += (fmono(v[i].x) >= mid) + (fmono(v[i].y) >= mid) +
                 (fmono(v[i].z) >= mid) + (fmono(v[i].w) >= mid);
        }
        #pragma unroll
        for (int j = 16; j >= 1; j >>= 1) c += __shfl_xor_sync(0xffffffffu, c, j);
        if (c >= KTOP) lo = mid; else hi = mid - 1u;
    }
    return fdemono(lo);   // exact 30th-largest value of this row
}

// ---------- one tensor row: sorted top-32 (per-lane) + threshold (30th largest) ----------
__device__ __forceinline__ float process_row(const float4 (&v)[8], unsigned lane,
                                             float* cand, float &thr) {
    float Tge = 1.42f;   // ~80 candidates expected for N(0,1); exact fallback below
    int c, base, total;
    count_scan(v, Tge, lane, c, base, total);
    if (total < KTOP || total > CAND_CAP) {
        Tge = find_thresh(v, lane);          // exact V30
        count_scan(v, Tge, lane, c, base, total);
    }
    // pad all 128 slots with -inf, then compact candidates
    ((float4*)cand)[lane] = make_float4(-CUDART_INF_F, -CUDART_INF_F,
                                        -CUDART_INF_F, -CUDART_INF_F);
    __syncwarp();
    int ptr = base;
    #pragma unroll
    for (int i = 0; i < 8; i++) {
        float e;
        e = v[i].x; if (e >= Tge) { if (ptr < CAND_CAP) cand[ptr] = e; ptr++; }
        e = v[i].y; if (e >= Tge) { if (ptr < CAND_CAP) cand[ptr] = e; ptr++; }
        e = v[i].z; if (e >= Tge) { if (ptr < CAND_CAP) cand[ptr] = e; ptr++; }
        e = v[i].w; if (e >= Tge) { if (ptr < CAND_CAP) cand[ptr] = e; ptr++; }
    }
    __syncwarp();
    float c0 = cand[lane];
    float c1 = cand[lane + 32];
    float c2 = cand[lane + 64];
    float c3 = cand[lane + 96];
    __syncwarp();
    float s = sort_top32(c0, c1, c2, c3, lane);
    thr = __shfl_sync(0xffffffffu, s, KTOP - 1);
    return s;
}

extern "C" __global__ void __launch_bounds__(TPB, 2)
topk_main(const float* __restrict__ pred, const float* __restrict__ target, int nrows) {
    __shared__ float s_cand[WPB][CAND_CAP];
    __shared__ float s_red[WPB][2];

    const unsigned lane = threadIdx.x & 31u;
    const unsigned warp = threadIdx.x >> 5;
    const int row = blockIdx.x * WPB + (int)warp;

    const float4* prow = (const float4*)pred   + (size_t)row * (COLS / 4);
    const float4* trow = (const float4*)target + (size_t)row * (COLS / 4);

    // front-batched loads for MLP; both rows stay register-resident
    float4 pv[8], tv[8];
    #pragma unroll
    for (int i = 0; i < 8; i++) pv[i] = prow[i * 32 + lane];
    #pragma unroll
    for (int i = 0; i < 8; i++) tv[i] = trow[i * 32 + lane];

    float thrp, thrt;
    float ps = process_row(pv, lane, s_cand[warp], thrp);
    float ts = process_row(tv, lane, s_cand[warp], thrt);

    // intersection of top-30 index sets == positions above both thresholds
    int cnt = 0;
    #pragma unroll
    for (int i = 0; i < 8; i++) {
        cnt += ((pv[i].x >= thrp) && (tv[i].x >= thrt));
        cnt += ((pv[i].y >= thrp) && (tv[i].y >= thrt));
        cnt += ((pv[i].z >= thrp) && (tv[i].z >= thrt));
        cnt += ((pv[i].w >= thrp) && (tv[i].w >= thrt));
    }
    #pragma unroll
    for (int j = 16; j >= 1; j >>= 1) cnt += __shfl_xor_sync(0xffffffffu, cnt, j);

    // sorted-value L1 diff: lane k holds k-th largest of both tensors
    float d = (lane < KTOP) ? fabsf(ps - ts) : 0.0f;
    #pragma unroll
    for (int j = 16; j >= 1; j >>= 1) d += __shfl_xor_sync(0xffffffffu, d, j);

    if (lane == 0) { s_red[warp][0] = (float)cnt; s_red[warp][1] = d; }
    __syncthreads();
    if (threadIdx.x < WPB) {
        float c = s_red[threadIdx.x][0];
        float dd = s_red[threadIdx.x][1];
        #pragma unroll
        for (int j = 4; j >= 1; j >>= 1) {
            c  += __shfl_xor_sync(0xffu, c, j);
            dd += __shfl_xor_sync(0xffu, dd, j);
        }
        if (threadIdx.x == 0) {
            g_pcnt[blockIdx.x]  = c;
            g_pdiff[blockIdx.x] = dd;
        }
    }
}

extern "C" __global__ void topk_reduce(float* out, int nblocks, int nrows) {
    __shared__ float sc[1024], sd[1024];
    int t = threadIdx.x;
    float c = 0.0f, d = 0.0f;
    for (int i = t; i < nblocks; i += 1024) { c += g_pcnt[i]; d += g_pdiff[i]; }
    sc[t] = c; sd[t] = d;
    __syncthreads();
    for (int s = 512; s >= 1; s >>= 1) {
        if (t < s) { sc[t] += sc[t + s]; sd[t] += sd[t + s]; }
        __syncthreads();
    }
    if (t == 0) {
        out[0] = sc[0] / (30.0f * (float)nrows);   // acc
        out[1] = sd[0] / 30.0f;                    // diff
    }
}

extern "C" void kernel_launch(void* const* d_in, const int* in_sizes, int n_in,
                              void* d_out, int out_size) {
    const float* pred   = (const float*)d_in[0];
    const float* target = (const float*)d_in[1];
    int nrows   = in_sizes[0] / COLS;
    int nblocks = nrows / WPB;
    topk_main<<<nblocks, TPB>>>(pred, target, nrows);
    topk_reduce<<<1, 1024>>>((float*)d_out, nblocks, nrows);
}

// round 2
// speedup vs baseline: 1.0552x; 1.0552x over previous
#include <cuda_runtime.h>
#include <cstdint>
#include <math_constants.h>

#define KTOP      30
#define COLS      1024
#define WPB       8            // warps (rows) per block
#define TPB       (WPB * 32)
#define MAX_BLOCKS 16384       // 131072 rows / 8
#define CAND_CAP  64           // candidate slots per warp (2 regs/lane in sort)

// deterministic partial sums (no device mallocs allowed)
__device__ float g_pcnt[MAX_BLOCKS];
__device__ float g_pdiff[MAX_BLOCKS];

// ---------- monotone float<->uint key (only used in the cold fallback) ----------
__device__ __forceinline__ unsigned fmono(float f) {
    unsigned u = __float_as_uint(f);
    return u ^ (0x80000000u | (unsigned)((int)u >> 31));
}
__device__ __forceinline__ float fdemono(unsigned k) {
    unsigned u = k ^ (0x80000000u | ~(unsigned)((int)k >> 31));
    return __uint_as_float(u);
}

// ---------- cross-lane bitonic: 2 regs/lane (64 values) -> top-32 sorted desc ----------
// returns s: lane k holds the (k+1)-th largest value of the 64 inputs
__device__ __forceinline__ float sort_top32_64(float v0, float v1, unsigned lane) {
    // Stage A: bitonic-sort each 32-slice; final k=32 stage leaves both descending.
    #pragma unroll
    for (int k = 2; k <= 32; k <<= 1) {
        #pragma unroll
        for (int j = k >> 1; j >= 1; j >>= 1) {
            bool wmax = (((lane & k) == 0) == ((lane & j) == 0));
            float o0 = __shfl_xor_sync(0xffffffffu, v0, j);
            float o1 = __shfl_xor_sync(0xffffffffu, v1, j);
            v0 = wmax ? fmaxf(v0, o0) : fminf(v0, o0);
            v1 = wmax ? fmaxf(v1, o1) : fminf(v1, o1);
        }
    }
    // Stage B: top-32 of two descending 32-lists: m[i] = max(a[i], b[31-i]) is the
    // top-32 multiset and bitonic; clean with a descending bitonic merge.
    float b1 = __shfl_sync(0xffffffffu, v1, 31 ^ lane);
    float s = fmaxf(v0, b1);
    #pragma unroll
    for (int j = 16; j >= 1; j >>= 1) {
        float o = __shfl_xor_sync(0xffffffffu, s, j);
        s = ((lane & j) == 0) ? fmaxf(s, o) : fminf(s, o);
    }
    return s;
}

// ---------- count elements >= Tge, warp-exclusive scan for compaction offsets ----------
__device__ __forceinline__ void count_scan(const float4 (&v)[8], float Tge, unsigned lane,
                                           int &cnt, int &base, int &total) {
    int c = 0;
    #pragma unroll
    for (int i = 0; i < 8; i++) {
        c += (v[i].x >= Tge) + (v[i].y >= Tge) + (v[i].z >= Tge) + (v[i].w >= Tge);
    }
    int incl = c;
    #pragma unroll
    for (int d = 1; d < 32; d <<= 1) {
        int n = __shfl_up_sync(0xffffffffu, incl, d);
        if ((int)lane >= d) incl += n;
    }
    total = __shfl_sync(0xffffffffu, incl, 31);
    base  = incl - c;
    cnt   = c;
}

// ---------- exact fallback: binary-search the 30th-largest value (cold path) ----------
__device__ __forceinline__ float find_thresh(const float4 (&v)[8], unsigned lane) {
    unsigned lo = 0u, hi = 0xFFFFFFFFu;   // invariant: count(key >= lo) >= KTOP
    while (lo < hi) {
        unsigned mid = lo + 1u + ((hi - lo - 1u) >> 1);   // overflow-safe upper mid
        int c = 0;
        #pragma unroll
        for (int i = 0; i < 8; i++) {
            c += (fmono(v[i].x) >= mid) + (fmono(v[i].y) >= mid) +
                 (fmono(v[i].z) >= mid) + (fmono(v[i].w) >= mid);
        }
        #pragma unroll
        for (int j = 16; j >= 1; j >>= 1) c += __shfl_xor_sync(0xffffffffu, c, j);
        if (c >= KTOP) lo = mid; else hi = mid - 1u;
    }
    return fdemono(lo);   // exact 30th-largest value of this row
}

// ---------- one tensor row: sorted top-32 (per-lane), threshold (30th largest),
// ---------- and per-lane positional membership bitmask (elem >= thr) ----------
__device__ __forceinline__ float process_row(const float4 (&v)[8], unsigned lane,
                                             float* cand, float &thr, unsigned &mask) {
    float Tge = 1.695f;   // ~46 candidates expected for N(0,1); exact fallback below
    int c, base, total;
    count_scan(v, Tge, lane, c, base, total);
    if (total < KTOP || total > CAND_CAP) {
        Tge = find_thresh(v, lane);          // exact V30
        count_scan(v, Tge, lane, c, base, total);
    }
    // pad all 64 slots with -inf, then compact candidates
    ((float2*)cand)[lane] = make_float2(-CUDART_INF_F, -CUDART_INF_F);
    __syncwarp();
    int ptr = base;
    #pragma unroll
    for (int i = 0; i < 8; i++) {
        float e;
        e = v[i].x; if (e >= Tge) { if (ptr < CAND_CAP) cand[ptr] = e; ptr++; }
        e = v[i].y; if (e >= Tge) { if (ptr < CAND_CAP) cand[ptr] = e; ptr++; }
        e = v[i].z; if (e >= Tge) { if (ptr < CAND_CAP) cand[ptr] = e; ptr++; }
        e = v[i].w; if (e >= Tge) { if (ptr < CAND_CAP) cand[ptr] = e; ptr++; }
    }
    __syncwarp();
    float c0 = cand[lane];
    float c1 = cand[lane + 32];
    __syncwarp();
    float s = sort_top32_64(c0, c1, lane);
    thr = __shfl_sync(0xffffffffu, s, KTOP - 1);
    // positional membership bitmask (same bit mapping for both tensors)
    unsigned m = 0;
    #pragma unroll
    for (int i = 0; i < 8; i++) {
        m |= (unsigned)(v[i].x >= thr) << (4 * i + 0);
        m |= (unsigned)(v[i].y >= thr) << (4 * i + 1);
        m |= (unsigned)(v[i].z >= thr) << (4 * i + 2);
        m |= (unsigned)(v[i].w >= thr) << (4 * i + 3);
    }
    mask = m;
    return s;
}

extern "C" __global__ void __launch_bounds__(TPB, 4)
topk_main(const float* __restrict__ pred, const float* __restrict__ target, int nrows) {
    __shared__ float s_cand[WPB][CAND_CAP];
    __shared__ float s_red[WPB][2];

    const unsigned lane = threadIdx.x & 31u;
    const unsigned warp = threadIdx.x >> 5;
    const int row = blockIdx.x * WPB + (int)warp;

    const float4* prow = (const float4*)pred   + (size_t)row * (COLS / 4);
    const float4* trow = (const float4*)target + (size_t)row * (COLS / 4);

    float thrp, thrt;
    unsigned mp, mt;
    float ps, ts;

    {   // pred row: registers die after the mask is formed
        float4 pv[8];
        #pragma unroll
        for (int i = 0; i < 8; i++) pv[i] = prow[i * 32 + lane];
        ps = process_row(pv, lane, s_cand[warp], thrp, mp);
    }
    {   // target row
        float4 tv[8];
        #pragma unroll
        for (int i = 0; i < 8; i++) tv[i] = trow[i * 32 + lane];
        ts = process_row(tv, lane, s_cand[warp], thrt, mt);
    }

    // intersection of top-30 index sets == positions above both thresholds
    int cnt = __popc(mp & mt);
    #pragma unroll
    for (int j = 16; j >= 1; j >>= 1) cnt += __shfl_xor_sync(0xffffffffu, cnt, j);

    // sorted-value L1 diff: lane k holds k-th largest of both tensors
    float d = (lane < KTOP) ? fabsf(ps - ts) : 0.0f;
    #pragma unroll
    for (int j = 16; j >= 1; j >>= 1) d += __shfl_xor_sync(0xffffffffu, d, j);

    if (lane == 0) { s_red[warp][0] = (float)cnt; s_red[warp][1] = d; }
    __syncthreads();
    if (threadIdx.x < WPB) {
        float c = s_red[threadIdx.x][0];
        float dd = s_red[threadIdx.x][1];
        #pragma unroll
        for (int j = 4; j >= 1; j >>= 1) {
            c  += __shfl_xor_sync(0xffu, c, j);
            dd += __shfl_xor_sync(0xffu, dd, j);
        }
        if (threadIdx.x == 0) {
            g_pcnt[blockIdx.x]  = c;
            g_pdiff[blockIdx.x] = dd;
        }
    }
}

extern "C" __global__ void topk_reduce(float* out, int nblocks, int nrows) {
    __shared__ float sc[1024], sd[1024];
    int t = threadIdx.x;
    float c = 0.0f, d = 0.0f;
    for (int i = t; i < nblocks; i += 1024) { c += g_pcnt[i]; d += g_pdiff[i]; }
    sc[t] = c; sd[t] = d;
    __syncthreads();
    for (int s = 512; s >= 1; s >>= 1) {
        if (t < s) { sc[t] += sc[t + s]; sd[t] += sd[t + s]; }
        __syncthreads();
    }
    if (t == 0) {
        out[0] = sc[0] / (30.0f * (float)nrows);   // acc
        out[1] = sd[0] / 30.0f;                    // diff
    }
}

extern "C" void kernel_launch(void* const* d_in, const int* in_sizes, int n_in,
                              void* d_out, int out_size) {
    const float* pred   = (const float*)d_in[0];
    const float* target = (const float*)d_in[1];
    int nrows   = in_sizes[0] / COLS;
    int nblocks = nrows / WPB;
    topk_main<<<nblocks, TPB>>>(pred, target, nrows);
    topk_reduce<<<1, 1024>>>((float*)d_out, nblocks, nrows);
}

// round 4
// speedup vs baseline: 1.0943x; 1.0370x over previous
#include <cuda_runtime.h>
#include <cstdint>
#include <math_constants.h>

#define KTOP   30
#define COLS   1024
#define WPB    8            // warps (rows) per block
#define TPB    (WPB * 32)
#define CAP    64           // hot-path candidate capacity (2 regs/lane in sort)
#define SLOTS  80           // padded storage (memory-safety clamp target)

// deterministic global accumulators (integer atomics commute exactly)
__device__ unsigned long long g_cnt;     // sum of per-row intersection counts
__device__ unsigned long long g_diffx;   // sum of per-block diff, fixed-point 2^30
__device__ unsigned g_arrive;

// ---------- monotone float<->uint key (only used in the cold fallback) ----------
__device__ __forceinline__ unsigned fmono(float f) {
    unsigned u = __float_as_uint(f);
    return u ^ (0x80000000u | (unsigned)((int)u >> 31));
}
__device__ __forceinline__ float fdemono(unsigned k) {
    unsigned u = k ^ (0x80000000u | ~(unsigned)((int)k >> 31));
    return __uint_as_float(u);
}

// ---------- cross-lane bitonic: 2 regs/lane (64 values) -> top-32 sorted desc ----------
// returns s: lane k holds the (k+1)-th largest of the 64 inputs
__device__ __forceinline__ float sort_top32_64(float v0, float v1, unsigned lane) {
    #pragma unroll
    for (int k = 2; k <= 32; k <<= 1) {
        #pragma unroll
        for (int j = k >> 1; j >= 1; j >>= 1) {
            bool wmax = (((lane & k) == 0) == ((lane & j) == 0));
            float o0 = __shfl_xor_sync(0xffffffffu, v0, j);
            float o1 = __shfl_xor_sync(0xffffffffu, v1, j);
            v0 = wmax ? fmaxf(v0, o0) : fminf(v0, o0);
            v1 = wmax ? fmaxf(v1, o1) : fminf(v1, o1);
        }
    }
    // top-32 of two descending 32-lists: max(a[i], b[31-i]) is bitonic; clean-merge.
    float b1 = __shfl_sync(0xffffffffu, v1, 31 ^ lane);
    float s = fmaxf(v0, b1);
    #pragma unroll
    for (int j = 16; j >= 1; j >>= 1) {
        float o = __shfl_xor_sync(0xffffffffu, s, j);
        s = ((lane & j) == 0) ? fmaxf(s, o) : fminf(s, o);
    }
    return s;
}

// ---------- exact fallback: binary-search the 30th-largest value (cold path) ----------
__device__ __forceinline__ float find_thresh(const float4 (&v)[8], unsigned lane) {
    unsigned lo = 0u, hi = 0xFFFFFFFFu;   // invariant: count(key >= lo) >= KTOP
    while (lo < hi) {
        unsigned mid = lo + 1u + ((hi - lo - 1u) >> 1);
        int c = 0;
        #pragma unroll
        for (int i = 0; i < 8; i++) {
            c += (fmono(v[i].x) >= mid) + (fmono(v[i].y) >= mid) +
                 (fmono(v[i].z) >= mid) + (fmono(v[i].w) >= mid);
        }
        #pragma unroll
        for (int j = 16; j >= 1; j >>= 1) c += __shfl_xor_sync(0xffffffffu, c, j);
        if (c >= KTOP) lo = mid; else hi = mid - 1u;
    }
    return fdemono(lo);   // exact 30th-largest value of this row
}

// ---------- ballot compaction: values + positions of elems >= Tge into shared ----------
// returns total count; uniform base lives in uniform registers
__device__ __forceinline__ int compact(const float4 (&v)[8], float Tge, unsigned lane,
                                       float* sv, unsigned short* sp) {
    int base = 0;
    const unsigned lt = (1u << lane) - 1u;
    #pragma unroll
    for (int i = 0; i < 8; i++) {
        const float e[4] = {v[i].x, v[i].y, v[i].z, v[i].w};
        #pragma unroll
        for (int c = 0; c < 4; c++) {
            bool p = e[c] >= Tge;
            unsigned b = __ballot_sync(0xffffffffu, p);
            int idx = min(base + __popc(b & lt), SLOTS - 1);   // clamp = mem safety
            if (p) { sv[idx] = e[c]; sp[idx] = (unsigned short)(128 * i + 4 * lane + c); }
            base += __popc(b);
        }
    }
    return base;
}

// ---------- one row: sorted top-32, threshold, candidate (value,pos) at lane slots ----
__device__ __forceinline__ float process_row(const float4 (&v)[8], unsigned lane,
                                             float* sv, unsigned short* sp, float &thr,
                                             float &cv0, float &cv1, int &p0, int &p1) {
    sv[lane]      = -CUDART_INF_F;          // pad 64 sort slots
    sv[lane + 32] = -CUDART_INF_F;
    __syncwarp();
    int total = compact(v, 1.695f, lane, sv, sp);   // ~46 expected for N(0,1)
    if (total < KTOP || total > CAP) {               // warp-uniform cold path (~1%)
        float T = find_thresh(v, lane);              // exact 30th-largest
        __syncwarp();
        sv[lane]      = -CUDART_INF_F;
        sv[lane + 32] = -CUDART_INF_F;
        __syncwarp();
        compact(v, T, lane, sv, sp);
    }
    __syncwarp();
    cv0 = sv[lane];       p0 = sp[lane];
    cv1 = sv[lane + 32];  p1 = sp[lane + 32];
    __syncwarp();
    float s = sort_top32_64(cv0, cv1, lane);
    thr = __shfl_sync(0xffffffffu, s, KTOP - 1);
    return s;
}

extern "C" __global__ void __launch_bounds__(TPB, 5)
topk_fused(const float* __restrict__ pred, const float* __restrict__ target,
           float* __restrict__ out, int nrows, int nblocks) {
    __shared__ float          s_v[WPB][SLOTS];
    __shared__ unsigned short s_p[WPB][SLOTS];
    __shared__ unsigned       s_bm[WPB][32];     // 1024-bit pred-membership bitmap
    __shared__ int            s_rc[WPB];
    __shared__ float          s_rd[WPB];

    const unsigned lane = threadIdx.x & 31u;
    const unsigned warp = threadIdx.x >> 5;
    const int row = blockIdx.x * WPB + (int)warp;

    const float4* prow = (const float4*)pred   + (size_t)row * (COLS / 4);
    const float4* trow = (const float4*)target + (size_t)row * (COLS / 4);

    s_bm[warp][lane] = 0u;   // syncwarp'ed inside process_row before first use

    float thrp, thrt, ps, ts, cv0, cv1;
    int p0, p1;

    {   // pred row — v registers die at the end of this scope
        float4 pv[8];
        #pragma unroll
        for (int i = 0; i < 8; i++) pv[i] = prow[i * 32 + lane];
        ps = process_row(pv, lane, s_v[warp], s_p[warp], thrp, cv0, cv1, p0, p1);
        // mark pred's top-30 positions (pads are -inf -> never >= thr)
        if (cv0 >= thrp) atomicOr(&s_bm[warp][p0 >> 5], 1u << (p0 & 31));
        if (cv1 >= thrp) atomicOr(&s_bm[warp][p1 >> 5], 1u << (p1 & 31));
    }
    __syncwarp();
    {   // target row
        float4 tv[8];
        #pragma unroll
        for (int i = 0; i < 8; i++) tv[i] = trow[i * 32 + lane];
        ts = process_row(tv, lane, s_v[warp], s_p[warp], thrt, cv0, cv1, p0, p1);
    }

    // intersection count: target's top-30 positions probe pred's bitmap
    int cnt = 0;
    if (cv0 >= thrt) cnt += (int)((s_bm[warp][p0 >> 5] >> (p0 & 31)) & 1u);
    if (cv1 >= thrt) cnt += (int)((s_bm[warp][p1 >> 5] >> (p1 & 31)) & 1u);
    cnt = __reduce_add_sync(0xffffffffu, cnt);

    // sorted-value L1 diff: lane k holds k-th largest of both tensors
    float d = (lane < KTOP) ? fabsf(ps - ts) : 0.0f;
    #pragma unroll
    for (int j = 16; j >= 1; j >>= 1) d += __shfl_xor_sync(0xffffffffu, d, j);

    if (lane == 0) { s_rc[warp] = cnt; s_rd[warp] = d; }
    __syncthreads();

    if (threadIdx.x == 0) {
        int   ci = 0;
        float df = 0.0f;
        #pragma unroll
        for (int w = 0; w < WPB; w++) { ci += s_rc[w]; df += s_rd[w]; }
        atomicAdd(&g_cnt, (unsigned long long)ci);
        atomicAdd(&g_diffx,
                  (unsigned long long)__double2ll_rn((double)df * 1073741824.0));
        __threadfence();
        unsigned t = atomicAdd(&g_arrive, 1u);
        if (t == (unsigned)(nblocks - 1)) {            // last block finalizes
            unsigned long long C = atomicAdd(&g_cnt, 0ULL);
            unsigned long long D = atomicAdd(&g_diffx, 0ULL);
            out[0] = (float)((double)C / (30.0 * (double)nrows));          // acc
            out[1] = (float)((double)D / (1073741824.0 * 30.0));           // diff
            g_cnt = 0ULL; g_diffx = 0ULL; g_arrive = 0u;   // reset for next replay
            __threadfence();
        }
    }
}

extern "C" void kernel_launch(void* const* d_in, const int* in_sizes, int n_in,
                              void* d_out, int out_size) {
    const float* pred   = (const float*)d_in[0];
    const float* target = (const float*)d_in[1];
    int nrows   = in_sizes[0] / COLS;
    int nblocks = nrows / WPB;
    topk_fused<<<nblocks, TPB>>>(pred, target, (float*)d_out, nrows, nblocks);
}

// round 5
// speedup vs baseline: 1.2906x; 1.1794x over previous
#include <cuda_runtime.h>
#include <cstdint>
#include <math_constants.h>

#define KTOP   30
#define COLS   1024
#define WPB    8            // warps (rows) per block
#define TPB    (WPB * 32)
#define CAP    64           // hot-path candidate capacity (2 regs/lane in sort)
#define SLOTS  80           // padded storage (memory-safety clamp target)

// deterministic global accumulators (integer atomics commute exactly)
__device__ unsigned long long g_cnt;     // sum of per-row intersection counts
__device__ unsigned long long g_diffx;   // sum of per-block diff, fixed-point 2^30
__device__ unsigned g_arrive;

// ---------- cp.async helpers ----------
__device__ __forceinline__ unsigned smem_u32(const void* p) {
    return (unsigned)__cvta_generic_to_shared(p);
}
__device__ __forceinline__ void cp_async16(unsigned saddr, const void* gptr) {
    asm volatile("cp.async.cg.shared.global [%0], [%1], 16;\n"
                 :: "r"(saddr), "l"(gptr) : "memory");
}
__device__ __forceinline__ void cp_commit() {
    asm volatile("cp.async.commit_group;\n" ::: "memory");
}
__device__ __forceinline__ void cp_wait0() {
    asm volatile("cp.async.wait_group 0;\n" ::: "memory");
}

// ---------- monotone float<->uint key (only used in the cold fallback) ----------
__device__ __forceinline__ unsigned fmono(float f) {
    unsigned u = __float_as_uint(f);
    return u ^ (0x80000000u | (unsigned)((int)u >> 31));
}
__device__ __forceinline__ float fdemono(unsigned k) {
    unsigned u = k ^ (0x80000000u | ~(unsigned)((int)k >> 31));
    return __uint_as_float(u);
}

// ---------- cross-lane bitonic: 2 regs/lane (64 values) -> top-32 sorted desc ----------
__device__ __forceinline__ float sort_top32_64(float v0, float v1, unsigned lane) {
    #pragma unroll
    for (int k = 2; k <= 32; k <<= 1) {
        #pragma unroll
        for (int j = k >> 1; j >= 1; j >>= 1) {
            bool wmax = (((lane & k) == 0) == ((lane & j) == 0));
            float o0 = __shfl_xor_sync(0xffffffffu, v0, j);
            float o1 = __shfl_xor_sync(0xffffffffu, v1, j);
            v0 = wmax ? fmaxf(v0, o0) : fminf(v0, o0);
            v1 = wmax ? fmaxf(v1, o1) : fminf(v1, o1);
        }
    }
    // top-32 of two descending 32-lists: max(a[i], b[31-i]) is bitonic; clean-merge.
    float b1 = __shfl_sync(0xffffffffu, v1, 31 ^ lane);
    float s = fmaxf(v0, b1);
    #pragma unroll
    for (int j = 16; j >= 1; j >>= 1) {
        float o = __shfl_xor_sync(0xffffffffu, s, j);
        s = ((lane & j) == 0) ? fmaxf(s, o) : fminf(s, o);
    }
    return s;
}

// ---------- exact fallback: binary-search the 30th-largest value (cold path) ----------
__device__ __forceinline__ float find_thresh(const float4 (&v)[8], unsigned lane) {
    unsigned lo = 0u, hi = 0xFFFFFFFFu;   // invariant: count(key >= lo) >= KTOP
    while (lo < hi) {
        unsigned mid = lo + 1u + ((hi - lo - 1u) >> 1);
        int c = 0;
        #pragma unroll
        for (int i = 0; i < 8; i++) {
            c += (fmono(v[i].x) >= mid) + (fmono(v[i].y) >= mid) +
                 (fmono(v[i].z) >= mid) + (fmono(v[i].w) >= mid);
        }
        #pragma unroll
        for (int j = 16; j >= 1; j >>= 1) c += __shfl_xor_sync(0xffffffffu, c, j);
        if (c >= KTOP) lo = mid; else hi = mid - 1u;
    }
    return fdemono(lo);   // exact 30th-largest value of this row
}

// ---------- ballot compaction: values + positions of elems >= Tge into shared ----------
__device__ __forceinline__ int compact(const float4 (&v)[8], float Tge, unsigned lane,
                                       float* sv, unsigned short* sp) {
    int base = 0;
    const unsigned lt = (1u << lane) - 1u;
    #pragma unroll
    for (int i = 0; i < 8; i++) {
        const float e[4] = {v[i].x, v[i].y, v[i].z, v[i].w};
        #pragma unroll
        for (int c = 0; c < 4; c++) {
            bool p = e[c] >= Tge;
            unsigned b = __ballot_sync(0xffffffffu, p);
            int idx = min(base + __popc(b & lt), SLOTS - 1);   // clamp = mem safety
            if (p) { sv[idx] = e[c]; sp[idx] = (unsigned short)(128 * i + 4 * lane + c); }
            base += __popc(b);
        }
    }
    return base;
}

// ---------- one row: sorted top-32, threshold, candidate (value,pos) at lane slots ----
__device__ __forceinline__ float process_row(const float4 (&v)[8], unsigned lane,
                                             float* sv, unsigned short* sp, float &thr,
                                             float &cv0, float &cv1, int &p0, int &p1) {
    sv[lane]      = -CUDART_INF_F;          // pad 64 sort slots
    sv[lane + 32] = -CUDART_INF_F;
    __syncwarp();
    int total = compact(v, 1.695f, lane, sv, sp);   // ~46 expected for N(0,1)
    if (total < KTOP || total > CAP) {               // warp-uniform cold path (~1%)
        float T = find_thresh(v, lane);              // exact 30th-largest
        __syncwarp();
        sv[lane]      = -CUDART_INF_F;
        sv[lane + 32] = -CUDART_INF_F;
        __syncwarp();
        compact(v, T, lane, sv, sp);
    }
    __syncwarp();
    cv0 = sv[lane];       p0 = sp[lane];
    cv1 = sv[lane + 32];  p1 = sp[lane + 32];
    __syncwarp();
    float s = sort_top32_64(cv0, cv1, lane);
    thr = __shfl_sync(0xffffffffu, s, KTOP - 1);
    return s;
}

extern "C" __global__ void __launch_bounds__(TPB, 5)
topk_fused(const float* __restrict__ pred, const float* __restrict__ target,
           float* __restrict__ out, int nrows, int nblocks) {
    __shared__ float4         s_trow[WPB][COLS / 4];   // cp.async staging, 32KB
    __shared__ float          s_v[WPB][SLOTS];
    __shared__ unsigned short s_p[WPB][SLOTS];
    __shared__ unsigned       s_bm[WPB][32];     // 1024-bit pred-membership bitmap
    __shared__ int            s_rc[WPB];
    __shared__ float          s_rd[WPB];

    const unsigned lane = threadIdx.x & 31u;
    const unsigned warp = threadIdx.x >> 5;
    const int row = blockIdx.x * WPB + (int)warp;

    const float4* prow = (const float4*)pred   + (size_t)row * (COLS / 4);
    const float4* trow = (const float4*)target + (size_t)row * (COLS / 4);

    // prefetch target row into shared (overlaps with pred processing)
    {
        unsigned sbase = smem_u32(&s_trow[warp][lane]);
        #pragma unroll
        for (int i = 0; i < 8; i++)
            cp_async16(sbase + (unsigned)(i * 32) * 16u, trow + i * 32 + lane);
        cp_commit();
    }

    s_bm[warp][lane] = 0u;   // syncwarp'ed inside process_row before first use

    float thrp, thrt, ps, ts, cv0, cv1;
    int p0, p1;

    {   // pred row — v registers die at the end of this scope
        float4 pv[8];
        #pragma unroll
        for (int i = 0; i < 8; i++) pv[i] = prow[i * 32 + lane];
        ps = process_row(pv, lane, s_v[warp], s_p[warp], thrp, cv0, cv1, p0, p1);
        // mark pred's top-30 positions (pads are -inf -> never >= thr)
        if (cv0 >= thrp) atomicOr(&s_bm[warp][p0 >> 5], 1u << (p0 & 31));
        if (cv1 >= thrp) atomicOr(&s_bm[warp][p1 >> 5], 1u << (p1 & 31));
    }
    cp_wait0();       // each thread reads exactly the bytes it copied
    __syncwarp();
    {   // target row from shared staging
        float4 tv[8];
        #pragma unroll
        for (int i = 0; i < 8; i++) tv[i] = s_trow[warp][i * 32 + lane];
        ts = process_row(tv, lane, s_v[warp], s_p[warp], thrt, cv0, cv1, p0, p1);
    }

    // intersection count: target's top-30 positions probe pred's bitmap
    int cnt = 0;
    if (cv0 >= thrt) cnt += (int)((s_bm[warp][p0 >> 5] >> (p0 & 31)) & 1u);
    if (cv1 >= thrt) cnt += (int)((s_bm[warp][p1 >> 5] >> (p1 & 31)) & 1u);
    cnt = __reduce_add_sync(0xffffffffu, cnt);

    // sorted-value L1 diff: lane k holds k-th largest of both tensors
    float d = (lane < KTOP) ? fabsf(ps - ts) : 0.0f;
    #pragma unroll
    for (int j = 16; j >= 1; j >>= 1) d += __shfl_xor_sync(0xffffffffu, d, j);

    if (lane == 0) { s_rc[warp] = cnt; s_rd[warp] = d; }
    __syncthreads();

    if (threadIdx.x == 0) {
        int   ci = 0;
        float df = 0.0f;
        #pragma unroll
        for (int w = 0; w < WPB; w++) { ci += s_rc[w]; df += s_rd[w]; }
        atomicAdd(&g_cnt, (unsigned long long)ci);
        atomicAdd(&g_diffx,
                  (unsigned long long)__double2ll_rn((double)df * 1073741824.0));
        __threadfence();
        unsigned t = atomicAdd(&g_arrive, 1u);
        if (t == (unsigned)(nblocks - 1)) {            // last block finalizes
            unsigned long long C = atomicAdd(&g_cnt, 0ULL);
            unsigned long long D = atomicAdd(&g_diffx, 0ULL);
            out[0] = (float)((double)C / (30.0 * (double)nrows));          // acc
            out[1] = (float)((double)D / (1073741824.0 * 30.0));           // diff
            g_cnt = 0ULL; g_diffx = 0ULL; g_arrive = 0u;   // reset for next replay
            __threadfence();
        }
    }
}

extern "C" void kernel_launch(void* const* d_in, const int* in_sizes, int n_in,
                              void* d_out, int out_size) {
    const float* pred   = (const float*)d_in[0];
    const float* target = (const float*)d_in[1];
    int nrows   = in_sizes[0] / COLS;
    int nblocks = nrows / WPB;
    topk_fused<<<nblocks, TPB>>>(pred, target, (float*)d_out, nrows, nblocks);
}

// round 6
// speedup vs baseline: 1.3844x; 1.0727x over previous
#include <cuda_runtime.h>
#include <cstdint>
#include <math_constants.h>

#define KTOP   30
#define COLS   1024
#define WPB    8            // warps (rows) per block
#define TPB    (WPB * 32)
#define CAP    64           // candidate slots per warp (2 regs/lane in sort)

// deterministic global accumulators (integer atomics commute exactly)
__device__ unsigned long long g_cnt;     // sum of per-row intersection counts
__device__ unsigned long long g_diffx;   // sum of per-block diff, fixed-point 2^30
__device__ unsigned g_arrive;

// ---------- cp.async helpers ----------
__device__ __forceinline__ unsigned smem_u32(const void* p) {
    return (unsigned)__cvta_generic_to_shared(p);
}
__device__ __forceinline__ void cp_async16(unsigned saddr, const void* gptr) {
    asm volatile("cp.async.cg.shared.global [%0], [%1], 16;\n"
                 :: "r"(saddr), "l"(gptr) : "memory");
}
__device__ __forceinline__ void cp_commit() {
    asm volatile("cp.async.commit_group;\n" ::: "memory");
}
__device__ __forceinline__ void cp_wait0() {
    asm volatile("cp.async.wait_group 0;\n" ::: "memory");
}

// ---------- monotone float<->uint key (only used in the cold fallback) ----------
__device__ __forceinline__ unsigned fmono(float f) {
    unsigned u = __float_as_uint(f);
    return u ^ (0x80000000u | (unsigned)((int)u >> 31));
}
__device__ __forceinline__ float fdemono(unsigned k) {
    unsigned u = k ^ (0x80000000u | ~(unsigned)((int)k >> 31));
    return __uint_as_float(u);
}

// ---------- cross-lane bitonic: 2 regs/lane (64 values) -> top-32 sorted desc ----------
__device__ __forceinline__ float sort_top32_64(float v0, float v1, unsigned lane) {
    #pragma unroll
    for (int k = 2; k <= 32; k <<= 1) {
        #pragma unroll
        for (int j = k >> 1; j >= 1; j >>= 1) {
            bool wmax = (((lane & k) == 0) == ((lane & j) == 0));
            float o0 = __shfl_xor_sync(0xffffffffu, v0, j);
            float o1 = __shfl_xor_sync(0xffffffffu, v1, j);
            v0 = wmax ? fmaxf(v0, o0) : fminf(v0, o0);
            v1 = wmax ? fmaxf(v1, o1) : fminf(v1, o1);
        }
    }
    // top-32 of two descending 32-lists: max(a[i], b[31-i]) is bitonic; clean-merge.
    float b1 = __shfl_sync(0xffffffffu, v1, 31 ^ lane);
    float s = fmaxf(v0, b1);
    #pragma unroll
    for (int j = 16; j >= 1; j >>= 1) {
        float o = __shfl_xor_sync(0xffffffffu, s, j);
        s = ((lane & j) == 0) ? fmaxf(s, o) : fminf(s, o);
    }
    return s;
}

// ---------- exact fallback: binary-search the 30th-largest value (cold path) ----------
__device__ __forceinline__ float find_thresh(const float4 (&v)[8], unsigned lane) {
    unsigned lo = 0u, hi = 0xFFFFFFFFu;   // invariant: count(key >= lo) >= KTOP
    while (lo < hi) {
        unsigned mid = lo + 1u + ((hi - lo - 1u) >> 1);
        int c = 0;
        #pragma unroll
        for (int i = 0; i < 8; i++) {
            c += (fmono(v[i].x) >= mid) + (fmono(v[i].y) >= mid) +
                 (fmono(v[i].z) >= mid) + (fmono(v[i].w) >= mid);
        }
        #pragma unroll
        for (int j = 16; j >= 1; j >>= 1) c += __shfl_xor_sync(0xffffffffu, c, j);
        if (c >= KTOP) lo = mid; else hi = mid - 1u;
    }
    return fdemono(lo);   // exact 30th-largest value of this row
}

// ---------- per-lane candidate mask (bit k = element k of this lane >= T) ----------
__device__ __forceinline__ unsigned build_mask(const float4 (&v)[8], float T) {
    unsigned m = 0u;
    #pragma unroll
    for (int i = 0; i < 8; i++) {
        if (v[i].x >= T) m |= 1u << (4 * i + 0);
        if (v[i].y >= T) m |= 1u << (4 * i + 1);
        if (v[i].z >= T) m |= 1u << (4 * i + 2);
        if (v[i].w >= T) m |= 1u << (4 * i + 3);
    }
    return m;
}

// ---------- warp exclusive scan over per-lane counts ----------
__device__ __forceinline__ int warp_exscan(int c, unsigned lane, int &total) {
    int incl = c;
    #pragma unroll
    for (int d = 1; d < 32; d <<= 1) {
        int n = __shfl_up_sync(0xffffffffu, incl, d);
        if ((int)lane >= d) incl += n;
    }
    total = __shfl_sync(0xffffffffu, incl, 31);
    return incl - c;
}

// ---------- ffs extraction: candidates -> packed (valbits,pos) u64 slots ----------
__device__ __forceinline__ void extract(unsigned m, int base, unsigned lane,
                                        const float* buf, unsigned long long* slot) {
    int idx = base;
    const unsigned lane4 = lane * 4u;
    while (__any_sync(0xffffffffu, m != 0u)) {
        if (m) {
            int k = __ffs(m) - 1;
            m &= m - 1u;
            int pos = ((k >> 2) << 7) | (int)(lane4 + (k & 3));   // 128*(k/4)+4*lane+(k%3..)
            float val = buf[pos];
            unsigned long long pk =
                ((unsigned long long)__float_as_uint(val) << 32) | (unsigned)pos;
            slot[idx & (CAP - 1)] = pk;     // wrap = mem safety; bad rows hit fallback
            idx++;
        }
    }
}

// ---------- candidate selection for one row resident in shared ----------
// fills slot[0..63] with packed (value,pos); pads are (-inf,0)
__device__ __forceinline__ void select_candidates(const float4 (&v)[8], unsigned lane,
                                                  const float* buf,
                                                  unsigned long long* slot) {
    const unsigned long long NEG = ((unsigned long long)0xFF800000u) << 32;  // -inf
    slot[lane]      = NEG;
    slot[lane + 32] = NEG;
    float T = 1.695f;                       // ~46 expected candidates for N(0,1)
    unsigned m = build_mask(v, T);
    int total, base = warp_exscan(__popc(m), lane, total);
    if (total < KTOP || total > CAP) {      // warp-uniform cold path (~1%)
        T = find_thresh(v, lane);           // exact 30th-largest
        m = build_mask(v, T);
        base = warp_exscan(__popc(m), lane, total);
    }
    __syncwarp();                           // pads visible before extraction writes
    extract(m, base, lane, buf, slot);
    __syncwarp();                           // slots complete
}

extern "C" __global__ void __launch_bounds__(TPB, 5)
topk_fused(const float* __restrict__ pred, const float* __restrict__ target,
           float* __restrict__ out, int nrows, int nblocks) {
    __shared__ float4             s_buf[WPB][COLS / 4];    // row staging, 32KB
    __shared__ unsigned long long s_slot[WPB][CAP];        // packed candidates, 4KB
    __shared__ unsigned           s_bm[WPB][32];           // pred membership bitmap
    __shared__ int                s_rc[WPB];
    __shared__ float              s_rd[WPB];

    const unsigned lane = threadIdx.x & 31u;
    const unsigned warp = threadIdx.x >> 5;
    const int row = blockIdx.x * WPB + (int)warp;

    const float4* prow = (const float4*)pred   + (size_t)row * (COLS / 4);
    const float4* trow = (const float4*)target + (size_t)row * (COLS / 4);
    const float*  buf  = (const float*)&s_buf[warp][0];
    unsigned long long* slot = &s_slot[warp][0];
    const unsigned sb = smem_u32(&s_buf[warp][0]);

    // prefetch pred row
    #pragma unroll
    for (int i = 0; i < 8; i++)
        cp_async16(sb + (unsigned)(i * 32 + lane) * 16u, prow + i * 32 + lane);
    cp_commit();

    s_bm[warp][lane] = 0u;

    float thrp, thrt, ps, ts;

    cp_wait0();
    __syncwarp();
    {   // ---- pred row ----
        float4 pv[8];
        #pragma unroll
        for (int i = 0; i < 8; i++) pv[i] = ((const float4*)buf)[i * 32 + lane];
        select_candidates(pv, lane, buf, slot);

        // buffer is dead: start fetching target NOW (overlaps pred sort below)
        #pragma unroll
        for (int i = 0; i < 8; i++)
            cp_async16(sb + (unsigned)(i * 32 + lane) * 16u, trow + i * 32 + lane);
        cp_commit();

        unsigned long long q0 = slot[lane], q1 = slot[lane + 32];
        float cv0 = __uint_as_float((unsigned)(q0 >> 32));
        float cv1 = __uint_as_float((unsigned)(q1 >> 32));
        int   p0  = (int)(q0 & 1023u), p1 = (int)(q1 & 1023u);

        ps = sort_top32_64(cv0, cv1, lane);
        thrp = __shfl_sync(0xffffffffu, ps, KTOP - 1);
        if (cv0 >= thrp) atomicOr(&s_bm[warp][p0 >> 5], 1u << (p0 & 31));
        if (cv1 >= thrp) atomicOr(&s_bm[warp][p1 >> 5], 1u << (p1 & 31));
    }
    cp_wait0();
    __syncwarp();

    int cnt;
    {   // ---- target row ----
        float4 tv[8];
        #pragma unroll
        for (int i = 0; i < 8; i++) tv[i] = ((const float4*)buf)[i * 32 + lane];
        select_candidates(tv, lane, buf, slot);

        unsigned long long q0 = slot[lane], q1 = slot[lane + 32];
        float cv0 = __uint_as_float((unsigned)(q0 >> 32));
        float cv1 = __uint_as_float((unsigned)(q1 >> 32));
        int   p0  = (int)(q0 & 1023u), p1 = (int)(q1 & 1023u);

        ts = sort_top32_64(cv0, cv1, lane);
        thrt = __shfl_sync(0xffffffffu, ts, KTOP - 1);

        cnt = 0;
        if (cv0 >= thrt) cnt += (int)((s_bm[warp][p0 >> 5] >> (p0 & 31)) & 1u);
        if (cv1 >= thrt) cnt += (int)((s_bm[warp][p1 >> 5] >> (p1 & 31)) & 1u);
        cnt = __reduce_add_sync(0xffffffffu, cnt);
    }

    // sorted-value L1 diff: lane k holds k-th largest of both tensors
    float d = (lane < KTOP) ? fabsf(ps - ts) : 0.0f;
    #pragma unroll
    for (int j = 16; j >= 1; j >>= 1) d += __shfl_xor_sync(0xffffffffu, d, j);

    if (lane == 0) { s_rc[warp] = cnt; s_rd[warp] = d; }
    __syncthreads();

    if (threadIdx.x == 0) {
        int   ci = 0;
        float df = 0.0f;
        #pragma unroll
        for (int w = 0; w < WPB; w++) { ci += s_rc[w]; df += s_rd[w]; }
        atomicAdd(&g_cnt, (unsigned long long)ci);
        atomicAdd(&g_diffx,
                  (unsigned long long)__double2ll_rn((double)df * 1073741824.0));
        __threadfence();
        unsigned t = atomicAdd(&g_arrive, 1u);
        if (t == (unsigned)(nblocks - 1)) {            // last block finalizes
            unsigned long long C = atomicAdd(&g_cnt, 0ULL);
            unsigned long long D = atomicAdd(&g_diffx, 0ULL);
            out[0] = (float)((double)C / (30.0 * (double)nrows));          // acc
            out[1] = (float)((double)D / (1073741824.0 * 30.0));           // diff
            g_cnt = 0ULL; g_diffx = 0ULL; g_arrive = 0u;   // reset for next replay
            __threadfence();
        }
    }
}

extern "C" void kernel_launch(void* const* d_in, const int* in_sizes, int n_in,
                              void* d_out, int out_size) {
    const float* pred   = (const float*)d_in[0];
    const float* target = (const float*)d_in[1];
    int nrows   = in_sizes[0] / COLS;
    int nblocks = nrows / WPB;
    topk_fused<<<nblocks, TPB>>>(pred, target, (float*)d_out, nrows, nblocks);
}

// round 7
// speedup vs baseline: 1.5181x; 1.0965x over previous
#include <cuda_runtime.h>
#include <cstdint>
#include <math_constants.h>

#define KTOP    30
#define COLS    1024
#define WPB     8            // warps per block
#define TPB     (WPB * 32)
#define CAP     64           // candidate slots per warp (2 regs/lane in sort)
#define NBLK    444          // 148 SMs x 3 resident blocks -> single persistent wave

// dynamic smem layout (bytes)
#define OFF_BUFA  0
#define OFF_BUFB  (WPB * COLS * 4)
#define OFF_SLOT  (2 * WPB * COLS * 4)
#define OFF_BM    (OFF_SLOT + WPB * CAP * 8)
#define SMEM_SZ   (OFF_BM + WPB * 32 * 4)

// deterministic global accumulators (integer atomics commute exactly)
__device__ unsigned long long g_cnt;     // sum of per-row intersection counts
__device__ unsigned long long g_diffx;   // sum of per-block diff, fixed-point 2^30
__device__ unsigned g_arrive;

// ---------- cp.async helpers ----------
__device__ __forceinline__ unsigned smem_u32(const void* p) {
    return (unsigned)__cvta_generic_to_shared(p);
}
__device__ __forceinline__ void cp_async16(unsigned saddr, const void* gptr) {
    asm volatile("cp.async.cg.shared.global [%0], [%1], 16;\n"
                 :: "r"(saddr), "l"(gptr) : "memory");
}
__device__ __forceinline__ void cp_commit() {
    asm volatile("cp.async.commit_group;\n" ::: "memory");
}
__device__ __forceinline__ void cp_wait1() {   // wait until <=1 group pending
    asm volatile("cp.async.wait_group 1;\n" ::: "memory");
}

// ---------- monotone float<->uint key (only used in the cold fallback) ----------
__device__ __forceinline__ unsigned fmono(float f) {
    unsigned u = __float_as_uint(f);
    return u ^ (0x80000000u | (unsigned)((int)u >> 31));
}
__device__ __forceinline__ float fdemono(unsigned k) {
    unsigned u = k ^ (0x80000000u | ~(unsigned)((int)k >> 31));
    return __uint_as_float(u);
}

// ---------- cross-lane bitonic: 2 regs/lane (64 values) -> top-32 sorted desc ----------
__device__ __forceinline__ float sort_top32_64(float v0, float v1, unsigned lane) {
    #pragma unroll
    for (int k = 2; k <= 32; k <<= 1) {
        #pragma unroll
        for (int j = k >> 1; j >= 1; j >>= 1) {
            bool wmax = (((lane & k) == 0) == ((lane & j) == 0));
            float o0 = __shfl_xor_sync(0xffffffffu, v0, j);
            float o1 = __shfl_xor_sync(0xffffffffu, v1, j);
            v0 = wmax ? fmaxf(v0, o0) : fminf(v0, o0);
            v1 = wmax ? fmaxf(v1, o1) : fminf(v1, o1);
        }
    }
    // top-32 of two descending 32-lists: max(a[i], b[31-i]) is bitonic; clean-merge.
    float b1 = __shfl_sync(0xffffffffu, v1, 31 ^ lane);
    float s = fmaxf(v0, b1);
    #pragma unroll
    for (int j = 16; j >= 1; j >>= 1) {
        float o = __shfl_xor_sync(0xffffffffu, s, j);
        s = ((lane & j) == 0) ? fmaxf(s, o) : fminf(s, o);
    }
    return s;
}

// ---------- exact fallback: binary-search the 30th-largest value (cold path) ----------
__device__ __forceinline__ float find_thresh(const float4 (&v)[8], unsigned lane) {
    unsigned lo = 0u, hi = 0xFFFFFFFFu;   // invariant: count(key >= lo) >= KTOP
    while (lo < hi) {
        unsigned mid = lo + 1u + ((hi - lo - 1u) >> 1);
        int c = 0;
        #pragma unroll
        for (int i = 0; i < 8; i++) {
            c += (fmono(v[i].x) >= mid) + (fmono(v[i].y) >= mid) +
                 (fmono(v[i].z) >= mid) + (fmono(v[i].w) >= mid);
        }
        #pragma unroll
        for (int j = 16; j >= 1; j >>= 1) c += __shfl_xor_sync(0xffffffffu, c, j);
        if (c >= KTOP) lo = mid; else hi = mid - 1u;
    }
    return fdemono(lo);   // exact 30th-largest value of this row
}

// ---------- per-lane candidate mask (bit k = element k of this lane >= T) ----------
__device__ __forceinline__ unsigned build_mask(const float4 (&v)[8], float T) {
    unsigned m = 0u;
    #pragma unroll
    for (int i = 0; i < 8; i++) {
        if (v[i].x >= T) m |= 1u << (4 * i + 0);
        if (v[i].y >= T) m |= 1u << (4 * i + 1);
        if (v[i].z >= T) m |= 1u << (4 * i + 2);
        if (v[i].w >= T) m |= 1u << (4 * i + 3);
    }
    return m;
}

// ---------- warp exclusive scan over per-lane counts ----------
__device__ __forceinline__ int warp_exscan(int c, unsigned lane, int &total) {
    int incl = c;
    #pragma unroll
    for (int d = 1; d < 32; d <<= 1) {
        int n = __shfl_up_sync(0xffffffffu, incl, d);
        if ((int)lane >= d) incl += n;
    }
    total = __shfl_sync(0xffffffffu, incl, 31);
    return incl - c;
}

// ---------- ffs extraction: candidates -> packed (valbits,pos) u64 slots ----------
__device__ __forceinline__ void extract(unsigned m, int base, unsigned lane,
                                        const float* buf, unsigned long long* slot) {
    int idx = base;
    const unsigned lane4 = lane * 4u;
    while (__any_sync(0xffffffffu, m != 0u)) {
        if (m) {
            int k = __ffs(m) - 1;
            m &= m - 1u;
            int pos = ((k >> 2) << 7) | (int)(lane4 + (k & 3));   // 128*(k/4)+4*lane+(k&3)
            float val = buf[pos];
            unsigned long long pk =
                ((unsigned long long)__float_as_uint(val) << 32) | (unsigned)pos;
            slot[idx & (CAP - 1)] = pk;     // wrap = mem safety; bad rows hit fallback
            idx++;
        }
    }
}

// ---------- candidate selection for one row resident in shared ----------
__device__ __forceinline__ void select_candidates(const float4 (&v)[8], unsigned lane,
                                                  const float* buf,
                                                  unsigned long long* slot) {
    const unsigned long long NEG = ((unsigned long long)0xFF800000u) << 32;  // -inf
    slot[lane]      = NEG;
    slot[lane + 32] = NEG;
    float T = 1.695f;                       // ~46 expected candidates for N(0,1)
    unsigned m = build_mask(v, T);
    int total, base = warp_exscan(__popc(m), lane, total);
    if (total < KTOP || total > CAP) {      // warp-uniform cold path (~1%)
        T = find_thresh(v, lane);           // exact 30th-largest
        m = build_mask(v, T);
        base = warp_exscan(__popc(m), lane, total);
    }
    __syncwarp();                           // pads visible before extraction writes
    extract(m, base, lane, buf, slot);
    __syncwarp();                           // slots complete
}

extern "C" __global__ void __launch_bounds__(TPB, 3)
topk_fused(const float* __restrict__ pred, const float* __restrict__ target,
           float* __restrict__ out, int nrows) {
    extern __shared__ unsigned char dsm[];
    __shared__ int   s_rc[WPB];
    __shared__ float s_rd[WPB];

    const unsigned lane = threadIdx.x & 31u;
    const unsigned warp = threadIdx.x >> 5;
    const int nwarps = NBLK * WPB;
    const int gw = blockIdx.x * WPB + (int)warp;

    float* bA = (float*)(dsm + OFF_BUFA) + warp * COLS;
    float* bB = (float*)(dsm + OFF_BUFB) + warp * COLS;
    unsigned long long* slot = (unsigned long long*)(dsm + OFF_SLOT) + warp * CAP;
    unsigned* bm = (unsigned*)(dsm + OFF_BM) + warp * 32;
    const unsigned sbA = smem_u32(bA);
    const unsigned sbB = smem_u32(bB);

    int   csum = 0;
    float dsum = 0.0f;

    // prologue: prefetch first row pair (two groups: pred, target)
    const float4* prow = (const float4*)pred   + (size_t)gw * (COLS / 4);
    const float4* trow = (const float4*)target + (size_t)gw * (COLS / 4);
    const size_t stride4 = (size_t)nwarps * (COLS / 4);
    #pragma unroll
    for (int i = 0; i < 8; i++)
        cp_async16(sbA + (unsigned)(i * 32 + lane) * 16u, prow + i * 32 + lane);
    cp_commit();
    #pragma unroll
    for (int i = 0; i < 8; i++)
        cp_async16(sbB + (unsigned)(i * 32 + lane) * 16u, trow + i * 32 + lane);
    cp_commit();

    for (int row = gw; row < nrows; row += nwarps) {
        const bool has_next = (row + nwarps) < nrows;
        bm[lane] = 0u;                      // ordered by syncwarps in select_candidates

        // ---- pred row (buffer A) ----
        cp_wait1();                          // pred_i landed (target_i may be in flight)
        __syncwarp();
        float ps, thrp;
        {
            float4 pv[8];
            #pragma unroll
            for (int i = 0; i < 8; i++) pv[i] = ((const float4*)bA)[i * 32 + lane];
            select_candidates(pv, lane, bA, slot);
        }
        // A is dead: prefetch next pred now (overlaps sort + target processing)
        prow += stride4;
        if (has_next) {
            #pragma unroll
            for (int i = 0; i < 8; i++)
                cp_async16(sbA + (unsigned)(i * 32 + lane) * 16u, prow + i * 32 + lane);
        }
        cp_commit();
        {
            unsigned long long q0 = slot[lane], q1 = slot[lane + 32];
            float cv0 = __uint_as_float((unsigned)(q0 >> 32));
            float cv1 = __uint_as_float((unsigned)(q1 >> 32));
            int   p0  = (int)(q0 & 1023u), p1 = (int)(q1 & 1023u);
            ps = sort_top32_64(cv0, cv1, lane);
            thrp = __shfl_sync(0xffffffffu, ps, KTOP - 1);
            if (cv0 >= thrp) atomicOr(&bm[p0 >> 5], 1u << (p0 & 31));
            if (cv1 >= thrp) atomicOr(&bm[p1 >> 5], 1u << (p1 & 31));
        }

        // ---- target row (buffer B) ----
        cp_wait1();                          // target_i landed (next pred in flight)
        __syncwarp();
        {
            float4 tv[8];
            #pragma unroll
            for (int i = 0; i < 8; i++) tv[i] = ((const float4*)bB)[i * 32 + lane];
            select_candidates(tv, lane, bB, slot);
        }
        trow += stride4;
        if (has_next) {
            #pragma unroll
            for (int i = 0; i < 8; i++)
                cp_async16(sbB + (unsigned)(i * 32 + lane) * 16u, trow + i * 32 + lane);
        }
        cp_commit();
        {
            unsigned long long q0 = slot[lane], q1 = slot[lane + 32];
            float cv0 = __uint_as_float((unsigned)(q0 >> 32));
            float cv1 = __uint_as_float((unsigned)(q1 >> 32));
            int   p0  = (int)(q0 & 1023u), p1 = (int)(q1 & 1023u);
            float ts = sort_top32_64(cv0, cv1, lane);
            float thrt = __shfl_sync(0xffffffffu, ts, KTOP - 1);

            int cnt = 0;
            if (cv0 >= thrt) cnt += (int)((bm[p0 >> 5] >> (p0 & 31)) & 1u);
            if (cv1 >= thrt) cnt += (int)((bm[p1 >> 5] >> (p1 & 31)) & 1u);
            csum += __reduce_add_sync(0xffffffffu, cnt);

            float d = (lane < KTOP) ? fabsf(ps - ts) : 0.0f;
            #pragma unroll
            for (int j = 16; j >= 1; j >>= 1) d += __shfl_xor_sync(0xffffffffu, d, j);
            dsum += d;
        }
    }

    if (lane == 0) { s_rc[warp] = csum; s_rd[warp] = dsum; }
    __syncthreads();

    if (threadIdx.x == 0) {
        int   ci = 0;
        float df = 0.0f;
        #pragma unroll
        for (int w = 0; w < WPB; w++) { ci += s_rc[w]; df += s_rd[w]; }
        atomicAdd(&g_cnt, (unsigned long long)ci);
        atomicAdd(&g_diffx,
                  (unsigned long long)__double2ll_rn((double)df * 1073741824.0));
        __threadfence();
        unsigned t = atomicAdd(&g_arrive, 1u);
        if (t == (unsigned)(NBLK - 1)) {               // last block finalizes
            unsigned long long C = atomicAdd(&g_cnt, 0ULL);
            unsigned long long D = atomicAdd(&g_diffx, 0ULL);
            out[0] = (float)((double)C / (30.0 * (double)nrows));          // acc
            out[1] = (float)((double)D / (1073741824.0 * 30.0));           // diff
            g_cnt = 0ULL; g_diffx = 0ULL; g_arrive = 0u;   // reset for next replay
            __threadfence();
        }
    }
}

extern "C" void kernel_launch(void* const* d_in, const int* in_sizes, int n_in,
                              void* d_out, int out_size) {
    const float* pred   = (const float*)d_in[0];
    const float* target = (const float*)d_in[1];
    int nrows = in_sizes[0] / COLS;
    cudaFuncSetAttribute(topk_fused, cudaFuncAttributeMaxDynamicSharedMemorySize,
                         SMEM_SZ);
    topk_fused<<<NBLK, TPB, SMEM_SZ>>>(pred, target, (float*)d_out, nrows);
}